// round 1
// baseline (speedup 1.0000x reference)
#include <cuda_runtime.h>

#define B_      256
#define IMG_    256
#define G_      64
#define HID_    512
#define NSTEP_  16
#define GATES_  (4*HID_)   // 2048
#define XDIM_   (G_*G_)    // 4096

// ---------------- scratch (static device globals; no allocation) -------------
__device__ float g_H[B_*HID_];
__device__ float g_C[B_*HID_];
__device__ float g_GP[B_*3];
__device__ float g_Fh[B_*IMG_*G_];   // (b, i, g) — g contiguous
__device__ float g_Fw[B_*IMG_*G_];
__device__ float g_X[B_*XDIM_];      // glimpse, flattened (gi*64+gj)
__device__ float g_gates[B_*GATES_];

// ---------------- init: zero H, C --------------------------------------------
__global__ void init_kernel() {
    int i = blockIdx.x * blockDim.x + threadIdx.x;
    if (i < B_*HID_) { g_H[i] = 0.f; g_C[i] = 0.f; }
}

// ---------------- gp = tanh(H @ W_g^T + b_g) : (B,3) -------------------------
__global__ void gp_kernel(const float* __restrict__ Wg, const float* __restrict__ bg) {
    int b = blockIdx.x;
    int w = threadIdx.x >> 5, lane = threadIdx.x & 31;
    if (w >= 3) return;
    const float* h  = g_H + b*HID_;
    const float* wr = Wg + w*HID_;
    float s = 0.f;
    #pragma unroll 4
    for (int k = lane; k < HID_; k += 32) s += h[k]*wr[k];
    #pragma unroll
    for (int o = 16; o; o >>= 1) s += __shfl_xor_sync(0xffffffffu, s, o);
    if (lane == 0) g_GP[b*3 + w] = tanhf(s + bg[w]);
}

// ---------------- filterbanks: F_h / F_w  (B, I=256, G=64) -------------------
// Pass 1: per-column sums (warp-per-glimpse-col). Pass 2: recompute Cauchy
// values (cheap MUFU) and write normalized, fully coalesced.
__global__ void filterbank_kernel() {
    __shared__ float s_r[G_];
    int b = blockIdx.x >> 1, axis = blockIdx.x & 1;
    float d  = g_GP[b*3 + 2];
    float cc = g_GP[b*3 + axis];
    float ad = fabsf(d);
    float center = 127.5f * (cc + 1.f);         // (I-1)*(c+1)/2
    float delta  = 4.f * (1.f - ad);            // I/G = 4
    float gamma  = expf(1.f - 2.f*ad);
    float inv_g  = 1.f / gamma;
    float amp    = 1.f / (3.14159265358979f * gamma);
    int warp = threadIdx.x >> 5, lane = threadIdx.x & 31;

    for (int gi = warp; gi < G_; gi += 8) {
        float mu = center + delta * ((float)gi - 31.5f);
        float s = 0.f;
        #pragma unroll
        for (int k = 0; k < 8; k++) {
            float u = ((float)(lane + 32*k) - mu) * inv_g;
            s += amp / (1.f + u*u);
        }
        #pragma unroll
        for (int o = 16; o; o >>= 1) s += __shfl_xor_sync(0xffffffffu, s, o);
        if (lane == 0) s_r[gi] = 1.f / (s + 1e-4f);
    }
    __syncthreads();

    float* out = (axis == 0 ? g_Fh : g_Fw) + (size_t)b * IMG_ * G_;
    for (int flat = threadIdx.x; flat < IMG_*G_; flat += 256) {
        int i = flat >> 6, gi = flat & 63;
        float mu = center + delta * ((float)gi - 31.5f);
        float u = ((float)i - mu) * inv_g;
        out[flat] = (amp / (1.f + u*u)) * s_r[gi];
    }
}

// ---------------- glimpse: x[b] = (F_h^T @ img @ F_w).flatten ----------------
// One CTA per sample, 256 threads.
// Phase 1: T[r][j] = sum_w img[r][w] * F_w[w][j]   (thread r owns 64 acc regs)
// Phase 2: g[i][j] = sum_r F_h[r][i] * T[r][j]     (thread owns col j, 16 i's)
extern __shared__ float gl_smem[];
__global__ void glimpse_kernel(const float* __restrict__ imgs, int ch) {
    float* s_F   = gl_smem;             // 16384 floats (F_w then F_h)
    float* s_buf = gl_smem + IMG_*G_;   // 16640 floats (img chunk pitch65 / T pitch64)
    int b = blockIdx.x;
    int t = threadIdx.x;
    const float* img = imgs + ((size_t)b*2 + ch) * IMG_*IMG_;
    const float* Fw  = g_Fw + (size_t)b * IMG_*G_;

    for (int k = t; k < IMG_*G_; k += 256) s_F[k] = Fw[k];

    float acc[64];
    #pragma unroll
    for (int j = 0; j < 64; j++) acc[j] = 0.f;

    for (int c = 0; c < 4; c++) {
        __syncthreads();                      // prev chunk compute done (also covers F load)
        const float4* src = (const float4*)(img + t*IMG_ + c*64);
        #pragma unroll
        for (int q = 0; q < 16; q++) {
            float4 v = src[q];
            int j = q*4;
            s_buf[t*65 + j  ] = v.x; s_buf[t*65 + j+1] = v.y;
            s_buf[t*65 + j+2] = v.z; s_buf[t*65 + j+3] = v.w;
        }
        __syncthreads();
        #pragma unroll 4
        for (int w = 0; w < 64; w++) {
            float a = s_buf[t*65 + w];                       // conflict-free (pitch 65)
            const float4* fw = (const float4*)&s_F[(c*64 + w)*64];   // broadcast
            #pragma unroll
            for (int q = 0; q < 16; q++) {
                float4 f = fw[q];
                acc[q*4+0] += a*f.x; acc[q*4+1] += a*f.y;
                acc[q*4+2] += a*f.z; acc[q*4+3] += a*f.w;
            }
        }
    }
    __syncthreads();
    // stash T (pitch 64), swap in F_h
    #pragma unroll 8
    for (int j = 0; j < 64; j++) s_buf[t*64 + j] = acc[j];
    const float* Fh = g_Fh + (size_t)b * IMG_*G_;
    for (int k = t; k < IMG_*G_; k += 256) s_F[k] = Fh[k];
    __syncthreads();

    int j = t & 63, i0 = (t >> 6) * 16;
    float acc2[16];
    #pragma unroll
    for (int i = 0; i < 16; i++) acc2[i] = 0.f;
    #pragma unroll 2
    for (int r = 0; r < IMG_; r++) {
        float a = s_buf[r*64 + j];                          // lanes j consecutive: conflict-free
        const float4* fh = (const float4*)&s_F[r*64 + i0];  // broadcast within warp
        #pragma unroll
        for (int q = 0; q < 4; q++) {
            float4 f = fh[q];
            acc2[q*4+0] += f.x*a; acc2[q*4+1] += f.y*a;
            acc2[q*4+2] += f.z*a; acc2[q*4+3] += f.w*a;
        }
    }
    float* xo = g_X + (size_t)b * XDIM_;
    #pragma unroll
    for (int i = 0; i < 16; i++) xo[(i0 + i)*64 + j] = acc2[i];   // coalesced
}

// ---------------- gates = X@Wih^T + H@Whh^T + b_ih + b_hh --------------------
// NT GEMM, tile 32(M)x64(N), 128 threads, 4x4 micro-tile, K chunks of 16.
__global__ void gates_kernel(const float* __restrict__ Wih, const float* __restrict__ Whh,
                             const float* __restrict__ bih, const float* __restrict__ bhh) {
    __shared__ float sA[32*17];
    __shared__ float sB[64*17];
    int m0 = blockIdx.y * 32, n0 = blockIdx.x * 64;
    int t = threadIdx.x;              // 0..127
    int tn = t & 15, tm = t >> 4;     // tm 0..7
    float acc[4][4];
    #pragma unroll
    for (int i = 0; i < 4; i++)
        #pragma unroll
        for (int jj = 0; jj < 4; jj++) acc[i][jj] = 0.f;

    int am  = t >> 2;   // 0..31
    int akq = t & 3;

    #pragma unroll 1
    for (int seg = 0; seg < 2; seg++) {
        const float* A  = (seg == 0) ? g_X : g_H;
        const float* Bm = (seg == 0) ? Wih : Whh;
        int K = (seg == 0) ? XDIM_ : HID_;
        #pragma unroll 1
        for (int k0 = 0; k0 < K; k0 += 16) {
            float4 av  = *(const float4*)&A [(size_t)(m0 + am)*K      + k0 + akq*4];
            float4 bv0 = *(const float4*)&Bm[(size_t)(n0 + am)*K      + k0 + akq*4];
            float4 bv1 = *(const float4*)&Bm[(size_t)(n0 + am + 32)*K + k0 + akq*4];
            __syncthreads();
            sA[am*17 + akq*4+0] = av.x;  sA[am*17 + akq*4+1] = av.y;
            sA[am*17 + akq*4+2] = av.z;  sA[am*17 + akq*4+3] = av.w;
            sB[am*17 + akq*4+0] = bv0.x; sB[am*17 + akq*4+1] = bv0.y;
            sB[am*17 + akq*4+2] = bv0.z; sB[am*17 + akq*4+3] = bv0.w;
            sB[(am+32)*17 + akq*4+0] = bv1.x; sB[(am+32)*17 + akq*4+1] = bv1.y;
            sB[(am+32)*17 + akq*4+2] = bv1.z; sB[(am+32)*17 + akq*4+3] = bv1.w;
            __syncthreads();
            #pragma unroll
            for (int k = 0; k < 16; k++) {
                float a0 = sA[(tm*4+0)*17 + k], a1 = sA[(tm*4+1)*17 + k];
                float a2 = sA[(tm*4+2)*17 + k], a3 = sA[(tm*4+3)*17 + k];
                float b0 = sB[(tn*4+0)*17 + k], b1 = sB[(tn*4+1)*17 + k];
                float b2 = sB[(tn*4+2)*17 + k], b3 = sB[(tn*4+3)*17 + k];
                acc[0][0] += a0*b0; acc[0][1] += a0*b1; acc[0][2] += a0*b2; acc[0][3] += a0*b3;
                acc[1][0] += a1*b0; acc[1][1] += a1*b1; acc[1][2] += a1*b2; acc[1][3] += a1*b3;
                acc[2][0] += a2*b0; acc[2][1] += a2*b1; acc[2][2] += a2*b2; acc[2][3] += a2*b3;
                acc[3][0] += a3*b0; acc[3][1] += a3*b1; acc[3][2] += a3*b2; acc[3][3] += a3*b3;
            }
        }
    }
    int n = n0 + tn*4;
    float bx = bih[n+0] + bhh[n+0];
    float by = bih[n+1] + bhh[n+1];
    float bz = bih[n+2] + bhh[n+2];
    float bw = bih[n+3] + bhh[n+3];
    #pragma unroll
    for (int i = 0; i < 4; i++) {
        int m = m0 + tm*4 + i;
        float4 v;
        v.x = acc[i][0] + bx; v.y = acc[i][1] + by;
        v.z = acc[i][2] + bz; v.w = acc[i][3] + bw;
        *(float4*)&g_gates[(size_t)m*GATES_ + n] = v;
    }
}

// ---------------- LSTM pointwise ---------------------------------------------
__global__ void lstm_kernel(float* out) {
    int idx = blockIdx.x * blockDim.x + threadIdx.x;    // < 131072
    int b = idx >> 9, h = idx & 511;
    const float* gr = g_gates + (size_t)b * GATES_;
    float xi = gr[h], xf = gr[HID_ + h], xg = gr[2*HID_ + h], xo = gr[3*HID_ + h];
    float si = 1.f / (1.f + expf(-xi));
    float sf = 1.f / (1.f + expf(-xf));
    float so = 1.f / (1.f + expf(-xo));
    float c = sf * g_C[idx] + si * tanhf(xg);
    float hh = so * tanhf(c);
    g_C[idx] = c; g_H[idx] = hh;
    if (out) out[idx] = hh;
}

// ---------------- launcher ----------------------------------------------------
extern "C" void kernel_launch(void* const* d_in, const int* in_sizes, int n_in,
                              void* d_out, int out_size) {
    const float* imgs = (const float*)d_in[0];
    const float* Wih  = (const float*)d_in[1];
    const float* Whh  = (const float*)d_in[2];
    const float* bih  = (const float*)d_in[3];
    const float* bhh  = (const float*)d_in[4];
    const float* Wg   = (const float*)d_in[5];
    const float* bg   = (const float*)d_in[6];
    float* out = (float*)d_out;

    size_t gl_bytes = (size_t)(IMG_*G_ + IMG_*65) * sizeof(float);  // 132096
    cudaFuncSetAttribute(glimpse_kernel, cudaFuncAttributeMaxDynamicSharedMemorySize,
                         (int)gl_bytes);

    init_kernel<<<(B_*HID_ + 255)/256, 256>>>();
    for (int t = 0; t < NSTEP_; t++) {
        gp_kernel<<<B_, 96>>>(Wg, bg);
        filterbank_kernel<<<2*B_, 256>>>();
        glimpse_kernel<<<B_, 256, gl_bytes>>>(imgs, t & 1);
        gates_kernel<<<dim3(GATES_/64, B_/32), 128>>>(Wih, Whh, bih, bhh);
        lstm_kernel<<<(B_*HID_)/256, 256>>>(t == NSTEP_-1 ? out : nullptr);
    }
}

// round 2
// speedup vs baseline: 1.1591x; 1.1591x over previous
#include <cuda_runtime.h>

#define B_      256
#define IMG_    256
#define G_      64
#define HID_    512
#define NSTEP_  16
#define GATES_  (4*HID_)   // 2048
#define XDIM_   (G_*G_)    // 4096
#define PI_     3.14159265358979f

// ---------------- scratch (static device globals; no allocation) -------------
__device__ float g_H[B_*HID_];
__device__ float g_C[B_*HID_];
__device__ float g_GP[B_*3];
__device__ float g_X[B_*XDIM_];
__device__ float g_gates[B_*GATES_];

// ---------------- init: zero H, C --------------------------------------------
__global__ void init_kernel() {
    int i = blockIdx.x * blockDim.x + threadIdx.x;
    if (i < B_*HID_) { g_H[i] = 0.f; g_C[i] = 0.f; }
}

// ---------------- gp = tanh(H @ W_g^T + b_g) : (B,3) -------------------------
__global__ void gp_kernel(const float* __restrict__ Wg, const float* __restrict__ bg) {
    int b = blockIdx.x;
    int w = threadIdx.x >> 5, lane = threadIdx.x & 31;
    if (w >= 3) return;
    const float* h  = g_H + b*HID_;
    const float* wr = Wg + w*HID_;
    float s = 0.f;
    #pragma unroll 4
    for (int k = lane; k < HID_; k += 32) s += h[k]*wr[k];
    #pragma unroll
    for (int o = 16; o; o >>= 1) s += __shfl_xor_sync(0xffffffffu, s, o);
    if (lane == 0) g_GP[b*3 + w] = tanhf(s + bg[w]);
}

// ---------------- fused filterbank + glimpse ---------------------------------
// One CTA per sample, 256 threads, 2 CTAs/SM.
// Computes UNNORMALIZED Cauchy filters in-kernel (amp cancels in normalization:
//   F = c / (S + 1e-4/amp),  c = 1/(1+u^2), S = col sum, amp = 1/(pi*gamma))
// and folds the per-column reciprocals into the GEMM epilogues.
// smem (floats):
//   s_F   [16640] : Fw unnorm (256x64, pitch 64) -> later T (256x64, pitch 65)
//   s_buf [ 8448] : img chunk (256x32, pitch 33) -> later Fh chunk (128x64, pitch 64)
//   s_rw  [64], s_rh [64], s_red [256]
#define GL_SF   0
#define GL_SBUF 16640
#define GL_SRW  (GL_SBUF + 8448)
#define GL_SRH  (GL_SRW + 64)
#define GL_SRED (GL_SRH + 64)
#define GL_TOT  (GL_SRED + 256)           // 25472 floats = 101888 bytes

extern __shared__ float gl_smem[];
__global__ __launch_bounds__(256, 2) void glimpse_kernel(const float* __restrict__ imgs, int ch) {
    float* s_F   = gl_smem + GL_SF;
    float* s_buf = gl_smem + GL_SBUF;
    float* s_rw  = gl_smem + GL_SRW;
    float* s_rh  = gl_smem + GL_SRH;
    float* s_red = gl_smem + GL_SRED;

    int b = blockIdx.x;
    int t = threadIdx.x;
    const float* img = imgs + ((size_t)b*2 + ch) * IMG_*IMG_;

    // filter params
    float d   = g_GP[b*3 + 2];
    float ch0 = g_GP[b*3 + 0];   // h center
    float cw  = g_GP[b*3 + 1];   // w center
    float ad      = fabsf(d);
    float delta   = 4.f * (1.f - ad);
    float gamma   = expf(1.f - 2.f*ad);
    float inv_g   = 1.f / gamma;
    float eps_adj = 1e-4f * PI_ * gamma;     // 1e-4 / amp
    float center_h = 127.5f * (ch0 + 1.f);
    float center_w = 127.5f * (cw  + 1.f);

    // ---- Fw unnormalized into s_F[w*64 + j] ----
    #pragma unroll
    for (int k = 0; k < 64; k++) {
        int flat = t + 256*k;
        int w = flat >> 6, j = flat & 63;
        float mu = center_w + delta * ((float)j - 31.5f);
        float u = ((float)w - mu) * inv_g;
        s_F[flat] = 1.f / (1.f + u*u);
    }
    __syncthreads();

    // ---- column-sum normalizers for Fw ----
    {
        int j = t & 63, part = t >> 6;
        float s = 0.f;
        #pragma unroll 8
        for (int w = part*64; w < part*64 + 64; w++) s += s_F[w*64 + j];
        s_red[t] = s;
    }
    __syncthreads();
    if (t < 64)
        s_rw[t] = 1.f / (s_red[t] + s_red[t+64] + s_red[t+128] + s_red[t+192] + eps_adj);

    // ---- phase 1: T[r][j] = sum_w img[r][w] * Fw_unnorm[w][j] ----
    float acc[64];
    #pragma unroll
    for (int j = 0; j < 64; j++) acc[j] = 0.f;

    for (int c = 0; c < 8; c++) {
        __syncthreads();
        const float4* src = (const float4*)(img + t*IMG_ + c*32);
        #pragma unroll
        for (int q = 0; q < 8; q++) {
            float4 v = src[q];
            int j = q*4;
            s_buf[t*33 + j  ] = v.x; s_buf[t*33 + j+1] = v.y;
            s_buf[t*33 + j+2] = v.z; s_buf[t*33 + j+3] = v.w;
        }
        __syncthreads();
        #pragma unroll 4
        for (int w = 0; w < 32; w++) {
            float a = s_buf[t*33 + w];
            const float4* fw = (const float4*)&s_F[(c*32 + w)*64];
            #pragma unroll
            for (int q = 0; q < 16; q++) {
                float4 f = fw[q];
                acc[q*4+0] += a*f.x; acc[q*4+1] += a*f.y;
                acc[q*4+2] += a*f.z; acc[q*4+3] += a*f.w;
            }
        }
    }
    __syncthreads();

    // ---- store T (pitch 65), folding Fw normalizer ----
    #pragma unroll 8
    for (int j = 0; j < 64; j++) s_F[t*65 + j] = acc[j] * s_rw[j];

    // ---- phase 2: x[i][j] = sum_r Fh_unnorm[r][i] * T[r][j], Fh in 2 chunks --
    int j2 = t & 63, i0 = (t >> 6) * 16;
    int gcol = t & 63;                          // Fh glimpse col this thread fills
    float mu_g = center_h + delta * ((float)gcol - 31.5f);
    float rh_part = 0.f;

    float acc2[16];
    #pragma unroll
    for (int i = 0; i < 16; i++) acc2[i] = 0.f;

    for (int cc = 0; cc < 2; cc++) {
        __syncthreads();
        int r0 = cc * 128;
        #pragma unroll
        for (int k = 0; k < 32; k++) {
            int flat = t + 256*k;               // rr = flat>>6, g = flat&63 (= gcol)
            int rr = flat >> 6;
            float u = ((float)(r0 + rr) - mu_g) * inv_g;
            float v = 1.f / (1.f + u*u);
            rh_part += v;
            s_buf[flat] = v;
        }
        __syncthreads();
        #pragma unroll 2
        for (int rr = 0; rr < 128; rr++) {
            float a = s_F[(r0 + rr)*65 + j2];
            const float4* fh = (const float4*)&s_buf[rr*64 + i0];
            #pragma unroll
            for (int q = 0; q < 4; q++) {
                float4 f = fh[q];
                acc2[q*4+0] += f.x*a; acc2[q*4+1] += f.y*a;
                acc2[q*4+2] += f.z*a; acc2[q*4+3] += f.w*a;
            }
        }
    }

    // ---- Fh normalizers ----
    s_red[t] = rh_part;
    __syncthreads();
    if (t < 64)
        s_rh[t] = 1.f / (s_red[t] + s_red[t+64] + s_red[t+128] + s_red[t+192] + eps_adj);
    __syncthreads();

    float* xo = g_X + (size_t)b * XDIM_;
    #pragma unroll
    for (int i = 0; i < 16; i++)
        xo[(i0 + i)*64 + j2] = acc2[i] * s_rh[i0 + i];
}

// ---------------- gates = X@Wih^T + H@Whh^T + b_ih + b_hh --------------------
// NT GEMM, tile 32(M)x64(N), 128 threads, 4x4 micro-tile.
// k-major smem (sA[k][m] pitch 36, sB[k][n] pitch 68) -> 2 LDS128 : 16 FFMA.
// Global loads prefetched across the k-loop.
__device__ __forceinline__ float4 ldA_(int m, int kA) {
    return (kA < XDIM_) ? *(const float4*)&g_X[(size_t)m*XDIM_ + kA]
                        : *(const float4*)&g_H[(size_t)m*HID_ + kA - XDIM_];
}
__global__ __launch_bounds__(128) void gates_kernel(
        const float* __restrict__ Wih, const float* __restrict__ Whh,
        const float* __restrict__ bih, const float* __restrict__ bhh) {
    __shared__ float sA[16*36];
    __shared__ float sB[16*68];
    int m0 = blockIdx.y * 32, n0 = blockIdx.x * 64;
    int t = threadIdx.x;
    int tn = t & 15, tm = t >> 4;
    int am = t >> 2, akq = t & 3;

    float acc[4][4];
    #pragma unroll
    for (int i = 0; i < 4; i++)
        #pragma unroll
        for (int jj = 0; jj < 4; jj++) acc[i][jj] = 0.f;

    const int KTOT = XDIM_ + HID_;   // 4608
    int kA = akq*4;
    float4 av  = ldA_(m0 + am, kA);
    float4 bv0 = (kA < XDIM_) ? *(const float4*)&Wih[(size_t)(n0+am)*XDIM_ + kA]
                              : *(const float4*)&Whh[(size_t)(n0+am)*HID_ + kA - XDIM_];
    float4 bv1 = (kA < XDIM_) ? *(const float4*)&Wih[(size_t)(n0+am+32)*XDIM_ + kA]
                              : *(const float4*)&Whh[(size_t)(n0+am+32)*HID_ + kA - XDIM_];

    for (int k0 = 0; k0 < KTOT; k0 += 16) {
        __syncthreads();
        int kr = akq*4;
        sA[(kr+0)*36 + am] = av.x; sA[(kr+1)*36 + am] = av.y;
        sA[(kr+2)*36 + am] = av.z; sA[(kr+3)*36 + am] = av.w;
        sB[(kr+0)*68 + am] = bv0.x; sB[(kr+1)*68 + am] = bv0.y;
        sB[(kr+2)*68 + am] = bv0.z; sB[(kr+3)*68 + am] = bv0.w;
        sB[(kr+0)*68 + am+32] = bv1.x; sB[(kr+1)*68 + am+32] = bv1.y;
        sB[(kr+2)*68 + am+32] = bv1.z; sB[(kr+3)*68 + am+32] = bv1.w;
        __syncthreads();

        int kn = k0 + 16 + akq*4;
        if (kn < KTOT) {
            av  = ldA_(m0 + am, kn);
            bv0 = (kn < XDIM_) ? *(const float4*)&Wih[(size_t)(n0+am)*XDIM_ + kn]
                               : *(const float4*)&Whh[(size_t)(n0+am)*HID_ + kn - XDIM_];
            bv1 = (kn < XDIM_) ? *(const float4*)&Wih[(size_t)(n0+am+32)*XDIM_ + kn]
                               : *(const float4*)&Whh[(size_t)(n0+am+32)*HID_ + kn - XDIM_];
        }

        #pragma unroll
        for (int k = 0; k < 16; k++) {
            float4 a = *(const float4*)&sA[k*36 + tm*4];
            float4 bb = *(const float4*)&sB[k*68 + tn*4];
            acc[0][0] += a.x*bb.x; acc[0][1] += a.x*bb.y; acc[0][2] += a.x*bb.z; acc[0][3] += a.x*bb.w;
            acc[1][0] += a.y*bb.x; acc[1][1] += a.y*bb.y; acc[1][2] += a.y*bb.z; acc[1][3] += a.y*bb.w;
            acc[2][0] += a.z*bb.x; acc[2][1] += a.z*bb.y; acc[2][2] += a.z*bb.z; acc[2][3] += a.z*bb.w;
            acc[3][0] += a.w*bb.x; acc[3][1] += a.w*bb.y; acc[3][2] += a.w*bb.z; acc[3][3] += a.w*bb.w;
        }
    }

    int n = n0 + tn*4;
    float bx = bih[n+0] + bhh[n+0];
    float by = bih[n+1] + bhh[n+1];
    float bz = bih[n+2] + bhh[n+2];
    float bw = bih[n+3] + bhh[n+3];
    #pragma unroll
    for (int i = 0; i < 4; i++) {
        int m = m0 + tm*4 + i;
        float4 v;
        v.x = acc[i][0] + bx; v.y = acc[i][1] + by;
        v.z = acc[i][2] + bz; v.w = acc[i][3] + bw;
        *(float4*)&g_gates[(size_t)m*GATES_ + n] = v;
    }
}

// ---------------- LSTM pointwise ---------------------------------------------
__global__ void lstm_kernel(float* out) {
    int idx = blockIdx.x * blockDim.x + threadIdx.x;    // < 131072
    int b = idx >> 9, h = idx & 511;
    const float* gr = g_gates + (size_t)b * GATES_;
    float xi = gr[h], xf = gr[HID_ + h], xg = gr[2*HID_ + h], xo = gr[3*HID_ + h];
    float si = 1.f / (1.f + expf(-xi));
    float sf = 1.f / (1.f + expf(-xf));
    float so = 1.f / (1.f + expf(-xo));
    float c = sf * g_C[idx] + si * tanhf(xg);
    float hh = so * tanhf(c);
    g_C[idx] = c; g_H[idx] = hh;
    if (out) out[idx] = hh;
}

// ---------------- launcher ----------------------------------------------------
extern "C" void kernel_launch(void* const* d_in, const int* in_sizes, int n_in,
                              void* d_out, int out_size) {
    const float* imgs = (const float*)d_in[0];
    const float* Wih  = (const float*)d_in[1];
    const float* Whh  = (const float*)d_in[2];
    const float* bih  = (const float*)d_in[3];
    const float* bhh  = (const float*)d_in[4];
    const float* Wg   = (const float*)d_in[5];
    const float* bg   = (const float*)d_in[6];
    float* out = (float*)d_out;

    size_t gl_bytes = (size_t)GL_TOT * sizeof(float);   // 101888 B -> 2 CTAs/SM
    cudaFuncSetAttribute(glimpse_kernel, cudaFuncAttributeMaxDynamicSharedMemorySize,
                         (int)gl_bytes);

    init_kernel<<<(B_*HID_ + 255)/256, 256>>>();
    for (int t = 0; t < NSTEP_; t++) {
        gp_kernel<<<B_, 96>>>(Wg, bg);
        glimpse_kernel<<<B_, 256, gl_bytes>>>(imgs, t & 1);
        gates_kernel<<<dim3(GATES_/64, B_/32), 128>>>(Wih, Whh, bih, bhh);
        lstm_kernel<<<(B_*HID_)/256, 256>>>(t == NSTEP_-1 ? out : nullptr);
    }
}

// round 5
// speedup vs baseline: 1.5839x; 1.3665x over previous
#include <cuda_runtime.h>
#include <cuda_fp16.h>
#include <cstdint>
#include <cstddef>

#define B_      256
#define IMG_    256
#define G_      64
#define HID_    512
#define NSTEP_  16
#define GATES_  (4*HID_)     // 2048
#define XDIM_   (G_*G_)      // 4096
#define KTOT_   (XDIM_+HID_) // 4608
#define PI_     3.14159265358979f

// ---------------- scratch (static device globals; no allocation) -------------
__device__ float g_H[B_*HID_];
__device__ float g_C[B_*HID_];
__device__ float g_GP[B_*3];
__device__ float g_gates[B_*GATES_];
// split operands for the tensor-core gates GEMM
__device__ __half g_Ahi[B_*KTOT_];      // rows b, cols [X | H]
__device__ __half g_Alo[B_*KTOT_];
__device__ __half g_Whi[GATES_*KTOT_];  // rows n, cols [Wih | Whh]
__device__ __half g_Wlo[GATES_*KTOT_];

#define LO_SCALE 2048.0f
#define LO_INV   4.8828125e-4f

__device__ __forceinline__ void split2(float v, __half& hi, __half& lo) {
    hi = __float2half_rn(v);
    lo = __float2half_rn((v - __half2float(hi)) * LO_SCALE);
}

// ---------------- init: zero H, C, and the whole A operand -------------------
__global__ void init_kernel() {
    int i = blockIdx.x * blockDim.x + threadIdx.x;
    if (i < B_*HID_) { g_H[i] = 0.f; g_C[i] = 0.f; }
    if (i < B_*KTOT_) {
        g_Ahi[i] = __float2half(0.f);
        g_Alo[i] = __float2half(0.f);
    }
}

// ---------------- pre-split W (once per launch; L2-resident after) -----------
__global__ void presplit_kernel(const float* __restrict__ Wih,
                                const float* __restrict__ Whh) {
    int n = blockIdx.x;
    for (int k = threadIdx.x; k < KTOT_; k += 256) {
        float w = (k < XDIM_) ? Wih[(size_t)n*XDIM_ + k]
                              : Whh[(size_t)n*HID_ + k - XDIM_];
        __half hi, lo; split2(w, hi, lo);
        g_Whi[(size_t)n*KTOT_ + k] = hi;
        g_Wlo[(size_t)n*KTOT_ + k] = lo;
    }
}

// ---------------- gp = tanh(H @ W_g^T + b_g) : (B,3) -------------------------
__global__ void gp_kernel(const float* __restrict__ Wg, const float* __restrict__ bg) {
    int b = blockIdx.x;
    int w = threadIdx.x >> 5, lane = threadIdx.x & 31;
    if (w >= 3) return;
    const float* h  = g_H + b*HID_;
    const float* wr = Wg + w*HID_;
    float s = 0.f;
    #pragma unroll 4
    for (int k = lane; k < HID_; k += 32) s += h[k]*wr[k];
    #pragma unroll
    for (int o = 16; o; o >>= 1) s += __shfl_xor_sync(0xffffffffu, s, o);
    if (lane == 0) g_GP[b*3 + w] = tanhf(s + bg[w]);
}

// ---------------- fused filterbank + glimpse (epilogue emits split X) --------
#define GL_SF   0
#define GL_SBUF 16640
#define GL_SRW  (GL_SBUF + 8448)
#define GL_SRH  (GL_SRW + 64)
#define GL_SRED (GL_SRH + 64)
#define GL_TOT  (GL_SRED + 256)           // 25472 floats = 101888 bytes

extern __shared__ float gl_smem[];
__global__ __launch_bounds__(256, 2) void glimpse_kernel(const float* __restrict__ imgs, int ch) {
    float* s_F   = gl_smem + GL_SF;
    float* s_buf = gl_smem + GL_SBUF;
    float* s_rw  = gl_smem + GL_SRW;
    float* s_rh  = gl_smem + GL_SRH;
    float* s_red = gl_smem + GL_SRED;

    int b = blockIdx.x;
    int t = threadIdx.x;
    const float* img = imgs + ((size_t)b*2 + ch) * IMG_*IMG_;

    float d   = g_GP[b*3 + 2];
    float ch0 = g_GP[b*3 + 0];
    float cw  = g_GP[b*3 + 1];
    float ad      = fabsf(d);
    float delta   = 4.f * (1.f - ad);
    float gamma   = expf(1.f - 2.f*ad);
    float inv_g   = 1.f / gamma;
    float eps_adj = 1e-4f * PI_ * gamma;
    float center_h = 127.5f * (ch0 + 1.f);
    float center_w = 127.5f * (cw  + 1.f);

    #pragma unroll
    for (int k = 0; k < 64; k++) {
        int flat = t + 256*k;
        int w = flat >> 6, j = flat & 63;
        float mu = center_w + delta * ((float)j - 31.5f);
        float u = ((float)w - mu) * inv_g;
        s_F[flat] = 1.f / (1.f + u*u);
    }
    __syncthreads();

    {
        int j = t & 63, part = t >> 6;
        float s = 0.f;
        #pragma unroll 8
        for (int w = part*64; w < part*64 + 64; w++) s += s_F[w*64 + j];
        s_red[t] = s;
    }
    __syncthreads();
    if (t < 64)
        s_rw[t] = 1.f / (s_red[t] + s_red[t+64] + s_red[t+128] + s_red[t+192] + eps_adj);

    float acc[64];
    #pragma unroll
    for (int j = 0; j < 64; j++) acc[j] = 0.f;

    for (int c = 0; c < 8; c++) {
        __syncthreads();
        const float4* src = (const float4*)(img + t*IMG_ + c*32);
        #pragma unroll
        for (int q = 0; q < 8; q++) {
            float4 v = src[q];
            int j = q*4;
            s_buf[t*33 + j  ] = v.x; s_buf[t*33 + j+1] = v.y;
            s_buf[t*33 + j+2] = v.z; s_buf[t*33 + j+3] = v.w;
        }
        __syncthreads();
        #pragma unroll 4
        for (int w = 0; w < 32; w++) {
            float a = s_buf[t*33 + w];
            const float4* fw = (const float4*)&s_F[(c*32 + w)*64];
            #pragma unroll
            for (int q = 0; q < 16; q++) {
                float4 f = fw[q];
                acc[q*4+0] += a*f.x; acc[q*4+1] += a*f.y;
                acc[q*4+2] += a*f.z; acc[q*4+3] += a*f.w;
            }
        }
    }
    __syncthreads();

    #pragma unroll 8
    for (int j = 0; j < 64; j++) s_F[t*65 + j] = acc[j] * s_rw[j];

    int j2 = t & 63, i0 = (t >> 6) * 16;
    int gcol = t & 63;
    float mu_g = center_h + delta * ((float)gcol - 31.5f);
    float rh_part = 0.f;

    float acc2[16];
    #pragma unroll
    for (int i = 0; i < 16; i++) acc2[i] = 0.f;

    for (int cc = 0; cc < 2; cc++) {
        __syncthreads();
        int r0 = cc * 128;
        #pragma unroll
        for (int k = 0; k < 32; k++) {
            int flat = t + 256*k;
            int rr = flat >> 6;
            float u = ((float)(r0 + rr) - mu_g) * inv_g;
            float v = 1.f / (1.f + u*u);
            rh_part += v;
            s_buf[flat] = v;
        }
        __syncthreads();
        #pragma unroll 2
        for (int rr = 0; rr < 128; rr++) {
            float a = s_F[(r0 + rr)*65 + j2];
            const float4* fh = (const float4*)&s_buf[rr*64 + i0];
            #pragma unroll
            for (int q = 0; q < 4; q++) {
                float4 f = fh[q];
                acc2[q*4+0] += f.x*a; acc2[q*4+1] += f.y*a;
                acc2[q*4+2] += f.z*a; acc2[q*4+3] += f.w*a;
            }
        }
    }

    s_red[t] = rh_part;
    __syncthreads();
    if (t < 64)
        s_rh[t] = 1.f / (s_red[t] + s_red[t+64] + s_red[t+128] + s_red[t+192] + eps_adj);
    __syncthreads();

    // epilogue: emit split fp16 X directly into the gates A operand
    __half* ahi = g_Ahi + (size_t)b * KTOT_;
    __half* alo = g_Alo + (size_t)b * KTOT_;
    #pragma unroll
    for (int i = 0; i < 16; i++) {
        float v = acc2[i] * s_rh[i0 + i];
        __half hi, lo; split2(v, hi, lo);
        ahi[(i0 + i)*64 + j2] = hi;
        alo[(i0 + i)*64 + j2] = lo;
    }
}

// ---------------- gates GEMM: mma.sync fp16x2, 2-stage cp.async ---------------
// C(256x2048) = A(256x4608) @ W^T.  CTA: 64 thr (2 warps), tile 32m x 64n.
#define AHOFF   0
#define ALOFF   2560
#define BHOFF   5120
#define BLOFF   10240
#define SSTAGE  15360
#define NKC     144     // 4608 / 32

__device__ __forceinline__ void cp16(uint32_t dst, const void* src) {
    asm volatile("cp.async.cg.shared.global [%0], [%1], 16;" :: "r"(dst), "l"(src));
}
__device__ __forceinline__ void ldsm4(uint32_t addr, uint32_t& r0, uint32_t& r1,
                                      uint32_t& r2, uint32_t& r3) {
    asm volatile("ldmatrix.sync.aligned.m8n8.x4.shared.b16 {%0,%1,%2,%3}, [%4];"
                 : "=r"(r0), "=r"(r1), "=r"(r2), "=r"(r3) : "r"(addr));
}
__device__ __forceinline__ void mma16816(float* c, uint32_t a0, uint32_t a1,
                                         uint32_t a2, uint32_t a3,
                                         uint32_t b0, uint32_t b1) {
    asm volatile("mma.sync.aligned.m16n8k16.row.col.f32.f16.f16.f32 "
                 "{%0,%1,%2,%3}, {%4,%5,%6,%7}, {%8,%9}, {%0,%1,%2,%3};"
                 : "+f"(c[0]), "+f"(c[1]), "+f"(c[2]), "+f"(c[3])
                 : "r"(a0), "r"(a1), "r"(a2), "r"(a3), "r"(b0), "r"(b1));
}

__global__ __launch_bounds__(64) void gates_kernel(
        const float* __restrict__ bih, const float* __restrict__ bhh) {
    __shared__ __align__(128) unsigned char gsm[2*SSTAGE];
    uint32_t sb = (uint32_t)__cvta_generic_to_shared(gsm);

    int t = threadIdx.x;
    int l = t & 31, wm = t >> 5;
    int m0 = blockIdx.y * 32, n0 = blockIdx.x * 64;

    int rA = (l & 7) + 8*((l >> 3) & 1) + wm*16;
    int cA = l >> 4;
    uint32_t aoffH = AHOFF + rA*80 + cA*16;
    uint32_t aoffL = ALOFF + rA*80 + cA*16;
    int rB = (l & 7) + 8*(l >> 4);
    int cB = (l >> 3) & 1;
    uint32_t boffH = BHOFF + rB*80 + cB*16;
    uint32_t boffL = BLOFF + rB*80 + cB*16;

    float chh[8][4], cmid[8][4];
    #pragma unroll
    for (int f = 0; f < 8; f++)
        #pragma unroll
        for (int q = 0; q < 4; q++) { chh[f][q] = 0.f; cmid[f][q] = 0.f; }

    auto issue = [&](int kc, int st) {
        uint32_t base = sb + st*SSTAGE;
        int k0 = kc * 32;
        #pragma unroll
        for (int j = 0; j < 2; j++) {              // A: 128 16B units
            int uid = t + 64*j;
            int row = uid >> 2, u = uid & 3;
            size_t gidx = (size_t)(m0 + row)*KTOT_ + k0 + u*8;
            uint32_t doff = row*80 + u*16;
            cp16(base + AHOFF + doff, g_Ahi + gidx);
            cp16(base + ALOFF + doff, g_Alo + gidx);
        }
        #pragma unroll
        for (int j = 0; j < 4; j++) {              // B: 256 16B units
            int uid = t + 64*j;
            int row = uid >> 2, u = uid & 3;
            size_t gidx = (size_t)(n0 + row)*KTOT_ + k0 + u*8;
            uint32_t doff = row*80 + u*16;
            cp16(base + BHOFF + doff, g_Whi + gidx);
            cp16(base + BLOFF + doff, g_Wlo + gidx);
        }
    };

    issue(0, 0); asm volatile("cp.async.commit_group;" ::: "memory");
    issue(1, 1); asm volatile("cp.async.commit_group;" ::: "memory");

    for (int kc = 0; kc < NKC; kc++) {
        int st = kc & 1;
        asm volatile("cp.async.wait_group 1;" ::: "memory");
        __syncthreads();
        uint32_t base = sb + st*SSTAGE;
        #pragma unroll
        for (int ks = 0; ks < 2; ks++) {
            uint32_t kb = ks*32;
            uint32_t aH0,aH1,aH2,aH3, aL0,aL1,aL2,aL3;
            ldsm4(base + aoffH + kb, aH0, aH1, aH2, aH3);
            ldsm4(base + aoffL + kb, aL0, aL1, aL2, aL3);
            #pragma unroll
            for (int p = 0; p < 4; p++) {
                uint32_t bH0,bH1,bH2,bH3, bL0,bL1,bL2,bL3;
                uint32_t poff = (uint32_t)(p*16*80) + kb;
                ldsm4(base + boffH + poff, bH0, bH1, bH2, bH3);
                ldsm4(base + boffL + poff, bL0, bL1, bL2, bL3);
                int f0 = 2*p, f1 = 2*p + 1;
                mma16816(chh[f0],  aH0,aH1,aH2,aH3, bH0,bH1);
                mma16816(chh[f1],  aH0,aH1,aH2,aH3, bH2,bH3);
                mma16816(cmid[f0], aL0,aL1,aL2,aL3, bH0,bH1);
                mma16816(cmid[f1], aL0,aL1,aL2,aL3, bH2,bH3);
                mma16816(cmid[f0], aH0,aH1,aH2,aH3, bL0,bL1);
                mma16816(cmid[f1], aH0,aH1,aH2,aH3, bL2,bL3);
            }
        }
        __syncthreads();
        if (kc + 2 < NKC) issue(kc + 2, st);
        asm volatile("cp.async.commit_group;" ::: "memory");
    }

    int g = l >> 2, tig = l & 3;
    int row0 = m0 + wm*16 + g, row1 = row0 + 8;
    #pragma unroll
    for (int f = 0; f < 8; f++) {
        int n = n0 + f*8 + tig*2;
        float b0 = bih[n]   + bhh[n];
        float b1 = bih[n+1] + bhh[n+1];
        float2 v0, v1;
        v0.x = chh[f][0] + cmid[f][0]*LO_INV + b0;
        v0.y = chh[f][1] + cmid[f][1]*LO_INV + b1;
        v1.x = chh[f][2] + cmid[f][2]*LO_INV + b0;
        v1.y = chh[f][3] + cmid[f][3]*LO_INV + b1;
        *(float2*)&g_gates[(size_t)row0*GATES_ + n] = v0;
        *(float2*)&g_gates[(size_t)row1*GATES_ + n] = v1;
    }
}

// ---------------- LSTM pointwise (emits split H into A) -----------------------
__global__ void lstm_kernel(float* out) {
    int idx = blockIdx.x * blockDim.x + threadIdx.x;    // < 131072
    int b = idx >> 9, h = idx & 511;
    const float* gr = g_gates + (size_t)b * GATES_;
    float xi = gr[h], xf = gr[HID_ + h], xg = gr[2*HID_ + h], xo = gr[3*HID_ + h];
    float si = 1.f / (1.f + expf(-xi));
    float sf = 1.f / (1.f + expf(-xf));
    float so = 1.f / (1.f + expf(-xo));
    float c = sf * g_C[idx] + si * tanhf(xg);
    float hh = so * tanhf(c);
    g_C[idx] = c; g_H[idx] = hh;
    __half hi, lo; split2(hh, hi, lo);
    g_Ahi[(size_t)b*KTOT_ + XDIM_ + h] = hi;
    g_Alo[(size_t)b*KTOT_ + XDIM_ + h] = lo;
    if (out) out[idx] = hh;
}

// ---------------- launcher ----------------------------------------------------
extern "C" void kernel_launch(void* const* d_in, const int* in_sizes, int n_in,
                              void* d_out, int out_size) {
    const float* imgs = (const float*)d_in[0];
    const float* Wih  = (const float*)d_in[1];
    const float* Whh  = (const float*)d_in[2];
    const float* bih  = (const float*)d_in[3];
    const float* bhh  = (const float*)d_in[4];
    const float* Wg   = (const float*)d_in[5];
    const float* bg   = (const float*)d_in[6];
    float* out = (float*)d_out;

    size_t gl_bytes = (size_t)GL_TOT * sizeof(float);   // 101888 B -> 2 CTAs/SM
    cudaFuncSetAttribute(glimpse_kernel, cudaFuncAttributeMaxDynamicSharedMemorySize,
                         (int)gl_bytes);

    init_kernel<<<(B_*KTOT_ + 255)/256, 256>>>();
    presplit_kernel<<<GATES_, 256>>>(Wih, Whh);
    for (int t = 0; t < NSTEP_; t++) {
        gp_kernel<<<B_, 96>>>(Wg, bg);
        glimpse_kernel<<<B_, 256, gl_bytes>>>(imgs, t & 1);
        gates_kernel<<<dim3(GATES_/64, B_/32), 64>>>(bih, bhh);
        lstm_kernel<<<(B_*HID_)/256, 256>>>(t == NSTEP_-1 ? out : nullptr);
    }
}

// round 10
// speedup vs baseline: 1.7231x; 1.0879x over previous
#include <cuda_runtime.h>
#include <cuda_fp16.h>
#include <cstdint>
#include <cstddef>

#define B_      256
#define IMG_    256
#define G_      64
#define HID_    512
#define NSTEP_  16
#define GATES_  (4*HID_)     // 2048
#define XDIM_   (G_*G_)      // 4096
#define KTOT_   (XDIM_+HID_) // 4608
#define PI_     3.14159265358979f

// ---------------- scratch (static device globals; no allocation) -------------
__device__ float g_H[B_*HID_];
__device__ float g_C[B_*HID_];
__device__ float g_GP[B_*3];
__device__ float g_gates[B_*GATES_];
// split operands for the tensor-core gates GEMM
__device__ __half g_Ahi[B_*KTOT_];      // rows b, cols [X | H]
__device__ __half g_Alo[B_*KTOT_];
__device__ __half g_Whi[GATES_*KTOT_];  // rows n, cols [Wih | Whh]
__device__ __half g_Wlo[GATES_*KTOT_];

#define LO_SCALE 2048.0f
#define LO_INV   4.8828125e-4f

__device__ __forceinline__ void split2(float v, __half& hi, __half& lo) {
    hi = __float2half_rn(v);
    lo = __float2half_rn((v - __half2float(hi)) * LO_SCALE);
}

__device__ __forceinline__ void cp16(uint32_t dst, const void* src) {
    asm volatile("cp.async.cg.shared.global [%0], [%1], 16;" :: "r"(dst), "l"(src));
}
__device__ __forceinline__ void cp8(uint32_t dst, const void* src) {
    asm volatile("cp.async.ca.shared.global [%0], [%1], 8;" :: "r"(dst), "l"(src));
}

// ---------------- init: zero H, C, and the whole A operand -------------------
__global__ void init_kernel() {
    int i = blockIdx.x * blockDim.x + threadIdx.x;
    if (i < B_*HID_) { g_H[i] = 0.f; g_C[i] = 0.f; }
    if (i < B_*KTOT_) {
        g_Ahi[i] = __float2half(0.f);
        g_Alo[i] = __float2half(0.f);
    }
}

// ---------------- pre-split W (once per launch; L2-resident after) -----------
__global__ void presplit_kernel(const float* __restrict__ Wih,
                                const float* __restrict__ Whh) {
    int n = blockIdx.x;
    for (int k = threadIdx.x; k < KTOT_; k += 256) {
        float w = (k < XDIM_) ? Wih[(size_t)n*XDIM_ + k]
                              : Whh[(size_t)n*HID_ + k - XDIM_];
        __half hi, lo; split2(w, hi, lo);
        g_Whi[(size_t)n*KTOT_ + k] = hi;
        g_Wlo[(size_t)n*KTOT_ + k] = lo;
    }
}

// ---------------- gp = tanh(H @ W_g^T + b_g) : (B,3) -------------------------
__global__ void gp_kernel(const float* __restrict__ Wg, const float* __restrict__ bg) {
    int b = blockIdx.x;
    int w = threadIdx.x >> 5, lane = threadIdx.x & 31;
    if (w >= 3) return;
    const float* h  = g_H + b*HID_;
    const float* wr = Wg + w*HID_;
    float s = 0.f;
    #pragma unroll 4
    for (int k = lane; k < HID_; k += 32) s += h[k]*wr[k];
    #pragma unroll
    for (int o = 16; o; o >>= 1) s += __shfl_xor_sync(0xffffffffu, s, o);
    if (lane == 0) g_GP[b*3 + w] = tanhf(s + bg[w]);
}

// ---------------- fused filterbank + glimpse, 512 threads --------------------
// phase 1 : thread = (row r = t>>1, j-half = (t&1)*32) -> acc[32]
// phase 2 : thread = (col j = t&63, i-block = (t>>6)*8) -> acc2[8]
// Image chunks (256 rows x 32 cols, pitch 34) double-buffered via 8B cp.async.
#define IMGP    34                       // image chunk pitch (floats)
#define IMGBUF  (IMG_*IMGP)              // 8704 floats per buffer
#define GL_SF    0
#define GL_IMG   16640
#define GL_RED   (GL_IMG + 2*IMGBUF)     // 16640 + 17408
#define GL_RW    (GL_RED + 512)
#define GL_RH    (GL_RW + 64)
#define GL_TOT   (GL_RH + 64)            // 34688 floats = 138752 bytes

extern __shared__ float gl_smem[];
__global__ __launch_bounds__(512, 1) void glimpse_kernel(const float* __restrict__ imgs, int ch) {
    float* s_F   = gl_smem + GL_SF;
    float* s_img = gl_smem + GL_IMG;
    float* s_red = gl_smem + GL_RED;
    float* s_rw  = gl_smem + GL_RW;
    float* s_rh  = gl_smem + GL_RH;
    uint32_t sb_img = (uint32_t)__cvta_generic_to_shared(s_img);

    int b = blockIdx.x;
    int t = threadIdx.x;
    const float* img = imgs + ((size_t)b*2 + ch) * IMG_*IMG_;

    int r     = t >> 1;          // phase-1 row
    int half  = t & 1;
    int jhalf = half * 32;

    // ---- start loading image chunks 0,1 immediately (8B cp.async, aligned) ----
    {
        const float* src0 = img + (size_t)r*IMG_ + 0*32 + half*16;
        uint32_t dst0 = sb_img + (uint32_t)((0*IMGBUF + r*IMGP + half*16) * 4);
        #pragma unroll
        for (int q = 0; q < 8; q++) cp8(dst0 + q*8, src0 + q*2);
        asm volatile("cp.async.commit_group;" ::: "memory");
        const float* src1 = img + (size_t)r*IMG_ + 1*32 + half*16;
        uint32_t dst1 = sb_img + (uint32_t)((1*IMGBUF + r*IMGP + half*16) * 4);
        #pragma unroll
        for (int q = 0; q < 8; q++) cp8(dst1 + q*8, src1 + q*2);
        asm volatile("cp.async.commit_group;" ::: "memory");
    }

    // ---- filter params ----
    float d   = g_GP[b*3 + 2];
    float ch0 = g_GP[b*3 + 0];
    float cw  = g_GP[b*3 + 1];
    float ad      = fabsf(d);
    float delta   = 4.f * (1.f - ad);
    float gamma   = expf(1.f - 2.f*ad);
    float inv_g   = 1.f / gamma;
    float eps_adj = 1e-4f * PI_ * gamma;
    float center_h = 127.5f * (ch0 + 1.f);
    float center_w = 127.5f * (cw  + 1.f);

    // ---- Fw unnorm into s_F[w*64+j] (overlaps with cp.async) ----
    #pragma unroll
    for (int k = 0; k < 32; k++) {
        int flat = t + 512*k;
        int w = flat >> 6, j = flat & 63;
        float mu = center_w + delta * ((float)j - 31.5f);
        float u = ((float)w - mu) * inv_g;
        s_F[flat] = 1.f / (1.f + u*u);
    }
    __syncthreads();

    // ---- Fw column-sum normalizers ----
    {
        int j = t & 63, part = t >> 6;           // 8 partials per column
        float s = 0.f;
        #pragma unroll 8
        for (int w = part*32; w < part*32 + 32; w++) s += s_F[w*64 + j];
        s_red[t] = s;
    }
    __syncthreads();
    if (t < 64) {
        float s = 0.f;
        #pragma unroll
        for (int p = 0; p < 8; p++) s += s_red[t + 64*p];
        s_rw[t] = 1.f / (s + eps_adj);
    }

    // ---- phase 1: T[r][j] = sum_w img[r][w] * Fw[w][j], 8 chunks ----
    float acc[32];
    #pragma unroll
    for (int j = 0; j < 32; j++) acc[j] = 0.f;

    for (int c = 0; c < 8; c++) {
        asm volatile("cp.async.wait_group 1;" ::: "memory");
        __syncthreads();
        const float* sib = s_img + (c & 1)*IMGBUF;
        #pragma unroll 2
        for (int w = 0; w < 32; w++) {
            float a = sib[r*IMGP + w];
            const float4* fw = (const float4*)&s_F[(c*32 + w)*64 + jhalf];
            #pragma unroll
            for (int q = 0; q < 8; q++) {
                float4 f = fw[q];
                acc[q*4+0] += a*f.x; acc[q*4+1] += a*f.y;
                acc[q*4+2] += a*f.z; acc[q*4+3] += a*f.w;
            }
        }
        __syncthreads();
        if (c + 2 < 8) {
            const float* src = img + (size_t)r*IMG_ + (c+2)*32 + half*16;
            uint32_t dst = sb_img + (uint32_t)((((c+2) & 1)*IMGBUF + r*IMGP + half*16) * 4);
            #pragma unroll
            for (int q = 0; q < 8; q++) cp8(dst + q*8, src + q*2);
        }
        asm volatile("cp.async.commit_group;" ::: "memory");
    }

    // ---- store T (pitch 65), fold Fw normalizer ----
    #pragma unroll 8
    for (int j = 0; j < 32; j++)
        s_F[r*65 + jhalf + j] = acc[j] * s_rw[jhalf + j];

    // ---- Fh unnorm into s_img[r*64+g] (all 256 rows) + partial sums ----
    {
        int g = t & 63, part = t >> 6;
        float mu = center_h + delta * ((float)g - 31.5f);
        float s = 0.f;
        #pragma unroll 8
        for (int rr = part*32; rr < part*32 + 32; rr++) {
            float u = ((float)rr - mu) * inv_g;
            float v = 1.f / (1.f + u*u);
            s += v;
            s_img[rr*64 + g] = v;
        }
        s_red[t] = s;
    }
    __syncthreads();
    if (t < 64) {
        float s = 0.f;
        #pragma unroll
        for (int p = 0; p < 8; p++) s += s_red[t + 64*p];
        s_rh[t] = 1.f / (s + eps_adj);
    }
    __syncthreads();

    // ---- phase 2: X[i][j] = sum_r Fh[r][i] * T[r][j] ----
    int j2 = t & 63, i0 = (t >> 6) * 8;
    float acc2[8];
    #pragma unroll
    for (int i = 0; i < 8; i++) acc2[i] = 0.f;
    #pragma unroll 4
    for (int rr = 0; rr < IMG_; rr++) {
        float a = s_F[rr*65 + j2];
        const float4* fh = (const float4*)&s_img[rr*64 + i0];
        float4 f0 = fh[0], f1 = fh[1];
        acc2[0] += f0.x*a; acc2[1] += f0.y*a; acc2[2] += f0.z*a; acc2[3] += f0.w*a;
        acc2[4] += f1.x*a; acc2[5] += f1.y*a; acc2[6] += f1.z*a; acc2[7] += f1.w*a;
    }

    // ---- epilogue: emit split fp16 X into gates A operand ----
    __half* ahi = g_Ahi + (size_t)b * KTOT_;
    __half* alo = g_Alo + (size_t)b * KTOT_;
    #pragma unroll
    for (int i = 0; i < 8; i++) {
        float v = acc2[i] * s_rh[i0 + i];
        __half hi, lo; split2(v, hi, lo);
        ahi[(i0 + i)*64 + j2] = hi;
        alo[(i0 + i)*64 + j2] = lo;
    }
}

// ---------------- gates GEMM: mma.sync fp16x2, 2-stage cp.async ---------------
// C(256x2048) = A(256x4608) @ W^T.  CTA: 64 thr (2 warps), tile 32m x 64n.
#define AHOFF   0
#define ALOFF   2560
#define BHOFF   5120
#define BLOFF   10240
#define SSTAGE  15360
#define NKC     144     // 4608 / 32

__device__ __forceinline__ void ldsm4(uint32_t addr, uint32_t& r0, uint32_t& r1,
                                      uint32_t& r2, uint32_t& r3) {
    asm volatile("ldmatrix.sync.aligned.m8n8.x4.shared.b16 {%0,%1,%2,%3}, [%4];"
                 : "=r"(r0), "=r"(r1), "=r"(r2), "=r"(r3) : "r"(addr));
}
__device__ __forceinline__ void mma16816(float* c, uint32_t a0, uint32_t a1,
                                         uint32_t a2, uint32_t a3,
                                         uint32_t b0, uint32_t b1) {
    asm volatile("mma.sync.aligned.m16n8k16.row.col.f32.f16.f16.f32 "
                 "{%0,%1,%2,%3}, {%4,%5,%6,%7}, {%8,%9}, {%0,%1,%2,%3};"
                 : "+f"(c[0]), "+f"(c[1]), "+f"(c[2]), "+f"(c[3])
                 : "r"(a0), "r"(a1), "r"(a2), "r"(a3), "r"(b0), "r"(b1));
}

__global__ __launch_bounds__(64) void gates_kernel(
        const float* __restrict__ bih, const float* __restrict__ bhh) {
    __shared__ __align__(128) unsigned char gsm[2*SSTAGE];
    uint32_t sb = (uint32_t)__cvta_generic_to_shared(gsm);

    int t = threadIdx.x;
    int l = t & 31, wm = t >> 5;
    int m0 = blockIdx.y * 32, n0 = blockIdx.x * 64;

    int rA = (l & 7) + 8*((l >> 3) & 1) + wm*16;
    int cA = l >> 4;
    uint32_t aoffH = AHOFF + rA*80 + cA*16;
    uint32_t aoffL = ALOFF + rA*80 + cA*16;
    int rB = (l & 7) + 8*(l >> 4);
    int cB = (l >> 3) & 1;
    uint32_t boffH = BHOFF + rB*80 + cB*16;
    uint32_t boffL = BLOFF + rB*80 + cB*16;

    float chh[8][4], cmid[8][4];
    #pragma unroll
    for (int f = 0; f < 8; f++)
        #pragma unroll
        for (int q = 0; q < 4; q++) { chh[f][q] = 0.f; cmid[f][q] = 0.f; }

    auto issue = [&](int kc, int st) {
        uint32_t base = sb + st*SSTAGE;
        int k0 = kc * 32;
        #pragma unroll
        for (int j = 0; j < 2; j++) {
            int uid = t + 64*j;
            int row = uid >> 2, u = uid & 3;
            size_t gidx = (size_t)(m0 + row)*KTOT_ + k0 + u*8;
            uint32_t doff = row*80 + u*16;
            cp16(base + AHOFF + doff, g_Ahi + gidx);
            cp16(base + ALOFF + doff, g_Alo + gidx);
        }
        #pragma unroll
        for (int j = 0; j < 4; j++) {
            int uid = t + 64*j;
            int row = uid >> 2, u = uid & 3;
            size_t gidx = (size_t)(n0 + row)*KTOT_ + k0 + u*8;
            uint32_t doff = row*80 + u*16;
            cp16(base + BHOFF + doff, g_Whi + gidx);
            cp16(base + BLOFF + doff, g_Wlo + gidx);
        }
    };

    issue(0, 0); asm volatile("cp.async.commit_group;" ::: "memory");
    issue(1, 1); asm volatile("cp.async.commit_group;" ::: "memory");

    for (int kc = 0; kc < NKC; kc++) {
        int st = kc & 1;
        asm volatile("cp.async.wait_group 1;" ::: "memory");
        __syncthreads();
        uint32_t base = sb + st*SSTAGE;
        #pragma unroll
        for (int ks = 0; ks < 2; ks++) {
            uint32_t kb = ks*32;
            uint32_t aH0,aH1,aH2,aH3, aL0,aL1,aL2,aL3;
            ldsm4(base + aoffH + kb, aH0, aH1, aH2, aH3);
            ldsm4(base + aoffL + kb, aL0, aL1, aL2, aL3);
            #pragma unroll
            for (int p = 0; p < 4; p++) {
                uint32_t bH0,bH1,bH2,bH3, bL0,bL1,bL2,bL3;
                uint32_t poff = (uint32_t)(p*16*80) + kb;
                ldsm4(base + boffH + poff, bH0, bH1, bH2, bH3);
                ldsm4(base + boffL + poff, bL0, bL1, bL2, bL3);
                int f0 = 2*p, f1 = 2*p + 1;
                mma16816(chh[f0],  aH0,aH1,aH2,aH3, bH0,bH1);
                mma16816(chh[f1],  aH0,aH1,aH2,aH3, bH2,bH3);
                mma16816(cmid[f0], aL0,aL1,aL2,aL3, bH0,bH1);
                mma16816(cmid[f1], aL0,aL1,aL2,aL3, bH2,bH3);
                mma16816(cmid[f0], aH0,aH1,aH2,aH3, bL0,bL1);
                mma16816(cmid[f1], aH0,aH1,aH2,aH3, bL2,bL3);
            }
        }
        __syncthreads();
        if (kc + 2 < NKC) issue(kc + 2, st);
        asm volatile("cp.async.commit_group;" ::: "memory");
    }

    int g = l >> 2, tig = l & 3;
    int row0 = m0 + wm*16 + g, row1 = row0 + 8;
    #pragma unroll
    for (int f = 0; f < 8; f++) {
        int n = n0 + f*8 + tig*2;
        float b0 = bih[n]   + bhh[n];
        float b1 = bih[n+1] + bhh[n+1];
        float2 v0, v1;
        v0.x = chh[f][0] + cmid[f][0]*LO_INV + b0;
        v0.y = chh[f][1] + cmid[f][1]*LO_INV + b1;
        v1.x = chh[f][2] + cmid[f][2]*LO_INV + b0;
        v1.y = chh[f][3] + cmid[f][3]*LO_INV + b1;
        *(float2*)&g_gates[(size_t)row0*GATES_ + n] = v0;
        *(float2*)&g_gates[(size_t)row1*GATES_ + n] = v1;
    }
}

// ---------------- LSTM pointwise (emits split H into A) -----------------------
__global__ void lstm_kernel(float* out) {
    int idx = blockIdx.x * blockDim.x + threadIdx.x;    // < 131072
    int b = idx >> 9, h = idx & 511;
    const float* gr = g_gates + (size_t)b * GATES_;
    float xi = gr[h], xf = gr[HID_ + h], xg = gr[2*HID_ + h], xo = gr[3*HID_ + h];
    float si = 1.f / (1.f + expf(-xi));
    float sf = 1.f / (1.f + expf(-xf));
    float so = 1.f / (1.f + expf(-xo));
    float c = sf * g_C[idx] + si * tanhf(xg);
    float hh = so * tanhf(c);
    g_C[idx] = c; g_H[idx] = hh;
    __half hi, lo; split2(hh, hi, lo);
    g_Ahi[(size_t)b*KTOT_ + XDIM_ + h] = hi;
    g_Alo[(size_t)b*KTOT_ + XDIM_ + h] = lo;
    if (out) out[idx] = hh;
}

// ---------------- launcher ----------------------------------------------------
extern "C" void kernel_launch(void* const* d_in, const int* in_sizes, int n_in,
                              void* d_out, int out_size) {
    const float* imgs = (const float*)d_in[0];
    const float* Wih  = (const float*)d_in[1];
    const float* Whh  = (const float*)d_in[2];
    const float* bih  = (const float*)d_in[3];
    const float* bhh  = (const float*)d_in[4];
    const float* Wg   = (const float*)d_in[5];
    const float* bg   = (const float*)d_in[6];
    float* out = (float*)d_out;

    size_t gl_bytes = (size_t)GL_TOT * sizeof(float);   // 138752 B, 1 CTA/SM
    cudaFuncSetAttribute(glimpse_kernel, cudaFuncAttributeMaxDynamicSharedMemorySize,
                         (int)gl_bytes);

    init_kernel<<<(B_*KTOT_ + 255)/256, 256>>>();
    presplit_kernel<<<GATES_, 256>>>(Wih, Whh);
    for (int t = 0; t < NSTEP_; t++) {
        gp_kernel<<<B_, 96>>>(Wg, bg);
        glimpse_kernel<<<B_, 512, gl_bytes>>>(imgs, t & 1);
        gates_kernel<<<dim3(GATES_/64, B_/32), 64>>>(bih, bhh);
        lstm_kernel<<<(B_*HID_)/256, 256>>>(t == NSTEP_-1 ? out : nullptr);
    }
}

// round 11
// speedup vs baseline: 3.5273x; 2.0471x over previous
#include <cuda_runtime.h>
#include <cuda_fp16.h>
#include <cstdint>
#include <cstddef>

#define B_      256
#define IMG_    256
#define G_      64
#define HID_    512
#define NSTEP_  16
#define GATES_  (4*HID_)     // 2048
#define XDIM_   (G_*G_)      // 4096
#define KTOT_   (XDIM_+HID_) // 4608
#define PI_     3.14159265358979f

// ---------------- scratch (static device globals; no allocation) -------------
__device__ float g_H[B_*HID_];
__device__ float g_C[B_*HID_];
__device__ float g_GP[B_*3];
__device__ float g_gates[B_*GATES_];
// split operands for the tensor-core gates GEMM
__device__ __half g_Ahi[B_*KTOT_];      // rows b, cols [X | H]
__device__ __half g_Alo[B_*KTOT_];
__device__ __half g_Whi[GATES_*KTOT_];  // rows n, cols [Wih | Whh]
__device__ __half g_Wlo[GATES_*KTOT_];
// split images (loop-invariant; split once per launch)
__device__ __half g_Ihi[B_*2*IMG_*IMG_];
__device__ __half g_Ilo[B_*2*IMG_*IMG_];

#define LO_SCALE 2048.0f
#define LO_INV   4.8828125e-4f

__device__ __forceinline__ void split2(float v, __half& hi, __half& lo) {
    hi = __float2half_rn(v);
    lo = __float2half_rn((v - __half2float(hi)) * LO_SCALE);
}

__device__ __forceinline__ void cp16(uint32_t dst, const void* src) {
    asm volatile("cp.async.cg.shared.global [%0], [%1], 16;" :: "r"(dst), "l"(src));
}
__device__ __forceinline__ void ldsm4(uint32_t addr, uint32_t& r0, uint32_t& r1,
                                      uint32_t& r2, uint32_t& r3) {
    asm volatile("ldmatrix.sync.aligned.m8n8.x4.shared.b16 {%0,%1,%2,%3}, [%4];"
                 : "=r"(r0), "=r"(r1), "=r"(r2), "=r"(r3) : "r"(addr));
}
__device__ __forceinline__ void mma16816(float* c, uint32_t a0, uint32_t a1,
                                         uint32_t a2, uint32_t a3,
                                         uint32_t b0, uint32_t b1) {
    asm volatile("mma.sync.aligned.m16n8k16.row.col.f32.f16.f16.f32 "
                 "{%0,%1,%2,%3}, {%4,%5,%6,%7}, {%8,%9}, {%0,%1,%2,%3};"
                 : "+f"(c[0]), "+f"(c[1]), "+f"(c[2]), "+f"(c[3])
                 : "r"(a0), "r"(a1), "r"(a2), "r"(a3), "r"(b0), "r"(b1));
}

// ---------------- init: zero H, C, and the whole A operand -------------------
__global__ void init_kernel() {
    int i = blockIdx.x * blockDim.x + threadIdx.x;
    if (i < B_*HID_) { g_H[i] = 0.f; g_C[i] = 0.f; }
    if (i < B_*KTOT_) {
        g_Ahi[i] = __float2half(0.f);
        g_Alo[i] = __float2half(0.f);
    }
}

// ---------------- pre-split W (once per launch) -------------------------------
__global__ void presplit_kernel(const float* __restrict__ Wih,
                                const float* __restrict__ Whh) {
    int n = blockIdx.x;
    for (int k = threadIdx.x; k < KTOT_; k += 256) {
        float w = (k < XDIM_) ? Wih[(size_t)n*XDIM_ + k]
                              : Whh[(size_t)n*HID_ + k - XDIM_];
        __half hi, lo; split2(w, hi, lo);
        g_Whi[(size_t)n*KTOT_ + k] = hi;
        g_Wlo[(size_t)n*KTOT_ + k] = lo;
    }
}

// ---------------- pre-split images (once per launch) --------------------------
__global__ void presplit_img_kernel(const float* __restrict__ imgs) {
    size_t base = (size_t)blockIdx.x * (IMG_*IMG_);
    for (int k = threadIdx.x; k < IMG_*IMG_; k += 256) {
        float v = imgs[base + k];
        __half hi, lo; split2(v, hi, lo);
        g_Ihi[base + k] = hi;
        g_Ilo[base + k] = lo;
    }
}

// ---------------- gp = tanh(H @ W_g^T + b_g) : (B,3) -------------------------
__global__ void gp_kernel(const float* __restrict__ Wg, const float* __restrict__ bg) {
    int b = blockIdx.x;
    int w = threadIdx.x >> 5, lane = threadIdx.x & 31;
    if (w >= 3) return;
    const float* h  = g_H + b*HID_;
    const float* wr = Wg + w*HID_;
    float s = 0.f;
    #pragma unroll 4
    for (int k = lane; k < HID_; k += 32) s += h[k]*wr[k];
    #pragma unroll
    for (int o = 16; o; o >>= 1) s += __shfl_xor_sync(0xffffffffu, s, o);
    if (lane == 0) g_GP[b*3 + w] = tanhf(s + bg[w]);
}

// ---------------- tensor-core glimpse: filterbank + 2 HMMA GEMMs -------------
// One CTA per sample, 512 threads (16 warps).
// Phase 1: T(256x64) = img @ Fw        (A streamed hi/lo, B = Fw_t resident)
// Phase 2: X(64x64)  = Fh^T @ T        (A = Fh_t, B = T_t, both smem)
// Filter rows stored [row][k] at 528B pitch (odd 16B units -> conflict-free LDSM).
// smem layout (bytes):
#define SM_FW_HI  0                      // 64 x 528  (Fw_t then Fh_t)
#define SM_FW_LO  33792
#define SM_IMG    67584                  // 2 x (256x80 hi + 256x80 lo) = 81920
#define SM_T_HI   67584                  // overlaps img bufs (phase handoff)
#define SM_T_LO   101376
#define SM_RED    149504                 // 512 floats
#define SM_RW     151552                 // 64 floats
#define SM_RH     151808                 // 64 floats
#define SM_TOTAL  152064

extern __shared__ char gl_smem[];
__global__ __launch_bounds__(512, 1) void glimpse_kernel(int ch) {
    uint32_t sb = (uint32_t)__cvta_generic_to_shared(gl_smem);
    float* s_red = (float*)(gl_smem + SM_RED);
    float* s_rw  = (float*)(gl_smem + SM_RW);
    float* s_rh  = (float*)(gl_smem + SM_RH);

    int b = blockIdx.x;
    int t = threadIdx.x;
    int l = t & 31, wid = t >> 5;
    // gates-proven lane constants
    int rA = (l & 7) + 8*((l >> 3) & 1);
    int cA = l >> 4;
    int rB = (l & 7) + 8*(l >> 4);
    int cB = (l >> 3) & 1;
    int g  = l >> 2, tig = l & 3;

    size_t ibase = ((size_t)b*2 + ch) * (IMG_*IMG_);   // half index base

    // ---- issue image k-chunks 0,1 (each: 256 rows x 32 halves, hi+lo) ----
    auto issue = [&](int cc) {
        int st = cc & 1;
        #pragma unroll
        for (int j = 0; j < 2; j++) {
            int uid = t + 512*j;                 // 1024 units of 16B (hi)
            int row = uid >> 2, u = uid & 3;
            size_t goff = ibase + (size_t)row*IMG_ + cc*32 + u*8;
            uint32_t doff = sb + SM_IMG + st*40960 + row*80 + u*16;
            cp16(doff, g_Ihi + goff);
            cp16(doff + 20480, g_Ilo + goff);
        }
    };
    issue(0); asm volatile("cp.async.commit_group;" ::: "memory");
    issue(1); asm volatile("cp.async.commit_group;" ::: "memory");

    // ---- filter params ----
    float d   = g_GP[b*3 + 2];
    float ch0 = g_GP[b*3 + 0];
    float cw  = g_GP[b*3 + 1];
    float ad      = fabsf(d);
    float delta   = 4.f * (1.f - ad);
    float gamma   = expf(1.f - 2.f*ad);
    float inv_g   = 1.f / gamma;
    float eps_adj = 1e-4f * PI_ * gamma;
    float center_h = 127.5f * (ch0 + 1.f);
    float center_w = 127.5f * (cw  + 1.f);

    // ---- generate Fw_t[j][w] (hi/lo) + partial column sums ----
    {
        int j = t & 63, wg = t >> 6;
        float mu = center_w + delta * ((float)j - 31.5f);
        __half* fh = (__half*)(gl_smem + SM_FW_HI) + j*264;
        __half* fl = (__half*)(gl_smem + SM_FW_LO) + j*264;
        float s = 0.f;
        #pragma unroll 8
        for (int w = wg*32; w < wg*32 + 32; w++) {
            float u = ((float)w - mu) * inv_g;
            float v = 1.f / (1.f + u*u);
            s += v;
            __half hi, lo; split2(v, hi, lo);
            fh[w] = hi; fl[w] = lo;
        }
        s_red[t] = s;
    }
    __syncthreads();
    if (t < 64) {
        float s = 0.f;
        #pragma unroll
        for (int p = 0; p < 8; p++) s += s_red[t + 64*p];
        s_rw[t] = 1.f / (s + eps_adj);
    }

    // ---- phase 1 mainloop: warp owns m-tile mt (rows mt*16..+15) ----
    int mt = wid;
    float chh[8][4], cmid[8][4];
    #pragma unroll
    for (int f = 0; f < 8; f++)
        #pragma unroll
        for (int q = 0; q < 4; q++) { chh[f][q] = 0.f; cmid[f][q] = 0.f; }

    for (int c = 0; c < 8; c++) {
        asm volatile("cp.async.wait_group 1;" ::: "memory");
        __syncthreads();
        uint32_t ahB = sb + SM_IMG + (c & 1)*40960 + (mt*16 + rA)*80 + cA*16;
        uint32_t alB = ahB + 20480;
        #pragma unroll
        for (int ks = 0; ks < 2; ks++) {
            uint32_t kb = ks*32;
            uint32_t aH0,aH1,aH2,aH3, aL0,aL1,aL2,aL3;
            ldsm4(ahB + kb, aH0, aH1, aH2, aH3);
            ldsm4(alB + kb, aL0, aL1, aL2, aL3);
            #pragma unroll
            for (int p = 0; p < 4; p++) {
                uint32_t bh = sb + SM_FW_HI + (uint32_t)((p*16 + rB)*528) + c*64 + cB*16 + kb;
                uint32_t bH0,bH1,bH2,bH3, bL0,bL1,bL2,bL3;
                ldsm4(bh, bH0, bH1, bH2, bH3);
                ldsm4(bh + 33792, bL0, bL1, bL2, bL3);
                int f0 = 2*p, f1 = 2*p + 1;
                mma16816(chh[f0],  aH0,aH1,aH2,aH3, bH0,bH1);
                mma16816(chh[f1],  aH0,aH1,aH2,aH3, bH2,bH3);
                mma16816(cmid[f0], aL0,aL1,aL2,aL3, bH0,bH1);
                mma16816(cmid[f1], aL0,aL1,aL2,aL3, bH2,bH3);
                mma16816(cmid[f0], aH0,aH1,aH2,aH3, bL0,bL1);
                mma16816(cmid[f1], aH0,aH1,aH2,aH3, bL2,bL3);
            }
        }
        __syncthreads();
        if (c + 2 < 8) issue(c + 2);
        asm volatile("cp.async.commit_group;" ::: "memory");
    }
    __syncthreads();   // all warps done reading img bufs (T overwrites them)

    // ---- T epilogue: fold rw, split, store transposed T_t[j][r] hi/lo ----
    {
        __half* th = (__half*)(gl_smem + SM_T_HI);
        __half* tl = (__half*)(gl_smem + SM_T_LO);
        #pragma unroll
        for (int f = 0; f < 8; f++) {
            #pragma unroll
            for (int q = 0; q < 4; q++) {
                int j = f*8 + tig*2 + (q & 1);
                int r = mt*16 + g + 8*(q >> 1);
                float val = (chh[f][q] + cmid[f][q]*LO_INV) * s_rw[j];
                __half hi, lo; split2(val, hi, lo);
                th[j*264 + r] = hi;
                tl[j*264 + r] = lo;
            }
        }
    }

    // ---- generate Fh_t[i][r] (hi/lo, overwrites Fw) + partial sums ----
    {
        int i = t & 63, rg = t >> 6;
        float mu = center_h + delta * ((float)i - 31.5f);
        __half* fh = (__half*)(gl_smem + SM_FW_HI) + i*264;
        __half* fl = (__half*)(gl_smem + SM_FW_LO) + i*264;
        float s = 0.f;
        #pragma unroll 8
        for (int r = rg*32; r < rg*32 + 32; r++) {
            float u = ((float)r - mu) * inv_g;
            float v = 1.f / (1.f + u*u);
            s += v;
            __half hi, lo; split2(v, hi, lo);
            fh[r] = hi; fl[r] = lo;
        }
        s_red[t] = s;
    }
    __syncthreads();
    if (t < 64) {
        float s = 0.f;
        #pragma unroll
        for (int p = 0; p < 8; p++) s += s_red[t + 64*p];
        s_rh[t] = 1.f / (s + eps_adj);
    }
    __syncthreads();

    // ---- phase 2: X = Fh_t @ T_t^T.  warp = (m-tile mt2, n-pair np) ----
    int mt2 = wid & 3, np = wid >> 2;
    float c2h[2][4], c2m[2][4];
    #pragma unroll
    for (int f = 0; f < 2; f++)
        #pragma unroll
        for (int q = 0; q < 4; q++) { c2h[f][q] = 0.f; c2m[f][q] = 0.f; }

    #pragma unroll 2
    for (int ks2 = 0; ks2 < 16; ks2++) {
        uint32_t kb = (uint32_t)ks2*32;
        uint32_t ah = sb + SM_FW_HI + (uint32_t)((mt2*16 + rA)*528) + kb + cA*16;
        uint32_t bh = sb + SM_T_HI  + (uint32_t)((np*16 + rB)*528) + kb + cB*16;
        uint32_t aH0,aH1,aH2,aH3, aL0,aL1,aL2,aL3;
        uint32_t bH0,bH1,bH2,bH3, bL0,bL1,bL2,bL3;
        ldsm4(ah, aH0, aH1, aH2, aH3);
        ldsm4(ah + 33792, aL0, aL1, aL2, aL3);
        ldsm4(bh, bH0, bH1, bH2, bH3);
        ldsm4(bh + 33792, bL0, bL1, bL2, bL3);
        mma16816(c2h[0], aH0,aH1,aH2,aH3, bH0,bH1);
        mma16816(c2h[1], aH0,aH1,aH2,aH3, bH2,bH3);
        mma16816(c2m[0], aL0,aL1,aL2,aL3, bH0,bH1);
        mma16816(c2m[1], aL0,aL1,aL2,aL3, bH2,bH3);
        mma16816(c2m[0], aH0,aH1,aH2,aH3, bL0,bL1);
        mma16816(c2m[1], aH0,aH1,aH2,aH3, bL2,bL3);
    }

    // ---- X epilogue: fold rh, split, emit into gates A operand ----
    {
        __half* ahi = g_Ahi + (size_t)b * KTOT_;
        __half* alo = g_Alo + (size_t)b * KTOT_;
        #pragma unroll
        for (int f = 0; f < 2; f++) {
            #pragma unroll
            for (int q = 0; q < 4; q++) {
                int i = mt2*16 + g + 8*(q >> 1);
                int j = np*16 + f*8 + tig*2 + (q & 1);
                float val = (c2h[f][q] + c2m[f][q]*LO_INV) * s_rh[i];
                __half hi, lo; split2(val, hi, lo);
                ahi[i*64 + j] = hi;
                alo[i*64 + j] = lo;
            }
        }
    }
}

// ---------------- gates GEMM: mma.sync fp16x2, 2-stage cp.async ---------------
#define AHOFF   0
#define ALOFF   2560
#define BHOFF   5120
#define BLOFF   10240
#define SSTAGE  15360
#define NKC     144     // 4608 / 32

__global__ __launch_bounds__(64) void gates_kernel(
        const float* __restrict__ bih, const float* __restrict__ bhh) {
    __shared__ __align__(128) unsigned char gsm[2*SSTAGE];
    uint32_t sb = (uint32_t)__cvta_generic_to_shared(gsm);

    int t = threadIdx.x;
    int l = t & 31, wm = t >> 5;
    int m0 = blockIdx.y * 32, n0 = blockIdx.x * 64;

    int rA = (l & 7) + 8*((l >> 3) & 1) + wm*16;
    int cA = l >> 4;
    uint32_t aoffH = AHOFF + rA*80 + cA*16;
    uint32_t aoffL = ALOFF + rA*80 + cA*16;
    int rB = (l & 7) + 8*(l >> 4);
    int cB = (l >> 3) & 1;
    uint32_t boffH = BHOFF + rB*80 + cB*16;
    uint32_t boffL = BLOFF + rB*80 + cB*16;

    float chh[8][4], cmid[8][4];
    #pragma unroll
    for (int f = 0; f < 8; f++)
        #pragma unroll
        for (int q = 0; q < 4; q++) { chh[f][q] = 0.f; cmid[f][q] = 0.f; }

    auto issue = [&](int kc, int st) {
        uint32_t base = sb + st*SSTAGE;
        int k0 = kc * 32;
        #pragma unroll
        for (int j = 0; j < 2; j++) {
            int uid = t + 64*j;
            int row = uid >> 2, u = uid & 3;
            size_t gidx = (size_t)(m0 + row)*KTOT_ + k0 + u*8;
            uint32_t doff = row*80 + u*16;
            cp16(base + AHOFF + doff, g_Ahi + gidx);
            cp16(base + ALOFF + doff, g_Alo + gidx);
        }
        #pragma unroll
        for (int j = 0; j < 4; j++) {
            int uid = t + 64*j;
            int row = uid >> 2, u = uid & 3;
            size_t gidx = (size_t)(n0 + row)*KTOT_ + k0 + u*8;
            uint32_t doff = row*80 + u*16;
            cp16(base + BHOFF + doff, g_Whi + gidx);
            cp16(base + BLOFF + doff, g_Wlo + gidx);
        }
    };

    issue(0, 0); asm volatile("cp.async.commit_group;" ::: "memory");
    issue(1, 1); asm volatile("cp.async.commit_group;" ::: "memory");

    for (int kc = 0; kc < NKC; kc++) {
        int st = kc & 1;
        asm volatile("cp.async.wait_group 1;" ::: "memory");
        __syncthreads();
        uint32_t base = sb + st*SSTAGE;
        #pragma unroll
        for (int ks = 0; ks < 2; ks++) {
            uint32_t kb = ks*32;
            uint32_t aH0,aH1,aH2,aH3, aL0,aL1,aL2,aL3;
            ldsm4(base + aoffH + kb, aH0, aH1, aH2, aH3);
            ldsm4(base + aoffL + kb, aL0, aL1, aL2, aL3);
            #pragma unroll
            for (int p = 0; p < 4; p++) {
                uint32_t bH0,bH1,bH2,bH3, bL0,bL1,bL2,bL3;
                uint32_t poff = (uint32_t)(p*16*80) + kb;
                ldsm4(base + boffH + poff, bH0, bH1, bH2, bH3);
                ldsm4(base + boffL + poff, bL0, bL1, bL2, bL3);
                int f0 = 2*p, f1 = 2*p + 1;
                mma16816(chh[f0],  aH0,aH1,aH2,aH3, bH0,bH1);
                mma16816(chh[f1],  aH0,aH1,aH2,aH3, bH2,bH3);
                mma16816(cmid[f0], aL0,aL1,aL2,aL3, bH0,bH1);
                mma16816(cmid[f1], aL0,aL1,aL2,aL3, bH2,bH3);
                mma16816(cmid[f0], aH0,aH1,aH2,aH3, bL0,bL1);
                mma16816(cmid[f1], aH0,aH1,aH2,aH3, bL2,bL3);
            }
        }
        __syncthreads();
        if (kc + 2 < NKC) issue(kc + 2, st);
        asm volatile("cp.async.commit_group;" ::: "memory");
    }

    int g = l >> 2, tig = l & 3;
    int row0 = m0 + wm*16 + g, row1 = row0 + 8;
    #pragma unroll
    for (int f = 0; f < 8; f++) {
        int n = n0 + f*8 + tig*2;
        float b0 = bih[n]   + bhh[n];
        float b1 = bih[n+1] + bhh[n+1];
        float2 v0, v1;
        v0.x = chh[f][0] + cmid[f][0]*LO_INV + b0;
        v0.y = chh[f][1] + cmid[f][1]*LO_INV + b1;
        v1.x = chh[f][2] + cmid[f][2]*LO_INV + b0;
        v1.y = chh[f][3] + cmid[f][3]*LO_INV + b1;
        *(float2*)&g_gates[(size_t)row0*GATES_ + n] = v0;
        *(float2*)&g_gates[(size_t)row1*GATES_ + n] = v1;
    }
}

// ---------------- LSTM pointwise (emits split H into A) -----------------------
__global__ void lstm_kernel(float* out) {
    int idx = blockIdx.x * blockDim.x + threadIdx.x;    // < 131072
    int b = idx >> 9, h = idx & 511;
    const float* gr = g_gates + (size_t)b * GATES_;
    float xi = gr[h], xf = gr[HID_ + h], xg = gr[2*HID_ + h], xo = gr[3*HID_ + h];
    float si = 1.f / (1.f + expf(-xi));
    float sf = 1.f / (1.f + expf(-xf));
    float so = 1.f / (1.f + expf(-xo));
    float c = sf * g_C[idx] + si * tanhf(xg);
    float hh = so * tanhf(c);
    g_C[idx] = c; g_H[idx] = hh;
    __half hi, lo; split2(hh, hi, lo);
    g_Ahi[(size_t)b*KTOT_ + XDIM_ + h] = hi;
    g_Alo[(size_t)b*KTOT_ + XDIM_ + h] = lo;
    if (out) out[idx] = hh;
}

// ---------------- launcher ----------------------------------------------------
extern "C" void kernel_launch(void* const* d_in, const int* in_sizes, int n_in,
                              void* d_out, int out_size) {
    const float* imgs = (const float*)d_in[0];
    const float* Wih  = (const float*)d_in[1];
    const float* Whh  = (const float*)d_in[2];
    const float* bih  = (const float*)d_in[3];
    const float* bhh  = (const float*)d_in[4];
    const float* Wg   = (const float*)d_in[5];
    const float* bg   = (const float*)d_in[6];
    float* out = (float*)d_out;

    cudaFuncSetAttribute(glimpse_kernel, cudaFuncAttributeMaxDynamicSharedMemorySize,
                         SM_TOTAL);

    init_kernel<<<(B_*KTOT_ + 255)/256, 256>>>();
    presplit_kernel<<<GATES_, 256>>>(Wih, Whh);
    presplit_img_kernel<<<B_*2, 256>>>(imgs);
    for (int t = 0; t < NSTEP_; t++) {
        gp_kernel<<<B_, 96>>>(Wg, bg);
        glimpse_kernel<<<B_, 512, SM_TOTAL>>>(t & 1);
        gates_kernel<<<dim3(GATES_/64, B_/32), 64>>>(bih, bhh);
        lstm_kernel<<<(B_*HID_)/256, 256>>>(t == NSTEP_-1 ? out : nullptr);
    }
}